// round 1
// baseline (speedup 1.0000x reference)
#include <cuda_runtime.h>

// ---------------------------------------------------------------------------
// 4-level db4 DWT low-pass cascade (analysis) + reconstruction (synthesis).
// One CTA per row; entire lo-chain lives in shared memory (ping-pong P/Q).
//
// Analysis stage (stride 2, 8 taps, pad 6 both sides, zero padding):
//   out[o] = sum_j DEC_LO[7-j] * in[2o + j - 6]
// Lengths: 32768 -> 16387 -> 8197 -> 4102 -> 2054      (pad = 6 at every level)
//
// Synthesis stage (2x lhs-dilation, 8 taps, pad (1,1)), polyphase split:
//   out[2q]   = g1*lo[q] + g3*lo[q+1] + g5*lo[q+2] + g7*lo[q+3]
//   out[2q+1] = g0*lo[q] + g2*lo[q+1] + g4*lo[q+2] + g6*lo[q+3]
//   out_len = 2*M - 6; q in [0, M-4]; no bounds checks needed.
// Chain: 2054 -> 4102 -> 8198 -(trim 8197)-> 16388 -(trim 16387)-> 32768
//
// season = x - trend, fused into final synthesis stage with float2 stores.
// ---------------------------------------------------------------------------

namespace {
constexpr int ROW_N = 32768;
constexpr int O1 = 16387, O2 = 8197, O3 = 4102, O4 = 2054;
constexpr int PCAP = 16388;                 // holds a1 (16387) / s3 (16388)
constexpr int QCAP = 8198;                  // holds a2 (8197) / a4 / s2 (8198)
constexpr int SMEM_BYTES = (PCAP + QCAP) * 4;   // 98,344 B -> 2 CTAs/SM
constexpr int NTHREADS = 1024;
}

__device__ __forceinline__ float wt_tap(const float* __restrict__ in, int i, int n) {
    return ((unsigned)i < (unsigned)n) ? in[i] : 0.0f;
}

// Analysis: one output sample. h[j] = DEC_LO[7-j].
__device__ __forceinline__ float wt_afb8(const float* __restrict__ in, int N, int o) {
    const int b = 2 * o - 6;
    float acc;
    acc  =  0.23037781330885523f   * wt_tap(in, b + 0, N);   // DEC_LO[7]
    acc +=  0.7148465705525415f    * wt_tap(in, b + 1, N);   // DEC_LO[6]
    acc +=  0.6308807679295904f    * wt_tap(in, b + 2, N);   // DEC_LO[5]
    acc += -0.02798376941698385f   * wt_tap(in, b + 3, N);   // DEC_LO[4]
    acc += -0.18703481171888114f   * wt_tap(in, b + 4, N);   // DEC_LO[3]
    acc +=  0.030841381835986965f  * wt_tap(in, b + 5, N);   // DEC_LO[2]
    acc +=  0.032883011666982945f  * wt_tap(in, b + 6, N);   // DEC_LO[1]
    acc += -0.010597401784997278f  * wt_tap(in, b + 7, N);   // DEC_LO[0]
    return acc;
}

// Synthesis: one even/odd output pair from 4 consecutive lo samples.
__device__ __forceinline__ void wt_sfb_pair(const float* __restrict__ in, int q,
                                            float& ev, float& od) {
    const float l0 = in[q], l1 = in[q + 1], l2 = in[q + 2], l3 = in[q + 3];
    // even output n=2q: taps g1,g3,g5,g7
    ev =  0.032883011666982945f  * l0
       + -0.18703481171888114f   * l1
       +  0.6308807679295904f    * l2
       +  0.23037781330885523f   * l3;
    // odd output n=2q+1: taps g0,g2,g4,g6
    od = -0.010597401784997278f  * l0
       +  0.030841381835986965f  * l1
       + -0.02798376941698385f   * l2
       +  0.7148465705525415f    * l3;
}

__global__ void __launch_bounds__(NTHREADS, 2)
wt_series_decomp_kernel(const float* __restrict__ x,
                        float* __restrict__ season,
                        float* __restrict__ trend)
{
    extern __shared__ float sm[];
    float* P = sm;              // capacity PCAP
    float* Q = sm + PCAP;       // capacity QCAP
    const int tid = threadIdx.x;
    const float* __restrict__ xr = x + (size_t)blockIdx.x * ROW_N;

    // ---- Analysis cascade ----
    // A1: x (global, 32768) -> P (16387)
    for (int o = tid; o < O1; o += NTHREADS) P[o] = wt_afb8(xr, ROW_N, o);
    __syncthreads();
    // A2: P (16387) -> Q (8197)
    for (int o = tid; o < O2; o += NTHREADS) Q[o] = wt_afb8(P, O1, o);
    __syncthreads();
    // A3: Q (8197) -> P (4102)   [a1 dead]
    for (int o = tid; o < O3; o += NTHREADS) P[o] = wt_afb8(Q, O2, o);
    __syncthreads();
    // A4: P (4102) -> Q (2054)   [a2 dead]
    for (int o = tid; o < O4; o += NTHREADS) Q[o] = wt_afb8(P, O3, o);
    __syncthreads();

    // ---- Synthesis cascade ----
    // S1: Q (2054) -> P (4102)   [a3 dead]
    for (int q = tid; q <= O4 - 4; q += NTHREADS) {
        float e, o; wt_sfb_pair(Q, q, e, o);
        *reinterpret_cast<float2*>(P + 2 * q) = make_float2(e, o);
    }
    __syncthreads();
    // S2: P (4102) -> Q (8198)   [a4 dead]
    for (int q = tid; q <= O3 - 4; q += NTHREADS) {
        float e, o; wt_sfb_pair(P, q, e, o);
        *reinterpret_cast<float2*>(Q + 2 * q) = make_float2(e, o);
    }
    __syncthreads();
    // S3: Q (trim to 8197) -> P (16388)   [s1 dead]
    for (int q = tid; q <= O2 - 4; q += NTHREADS) {
        float e, o; wt_sfb_pair(Q, q, e, o);
        *reinterpret_cast<float2*>(P + 2 * q) = make_float2(e, o);
    }
    __syncthreads();
    // S4: P (trim to 16387) -> trend (32768); season = x - trend. Fused, float2.
    float2* __restrict__ tr2 = reinterpret_cast<float2*>(trend + (size_t)blockIdx.x * ROW_N);
    float2* __restrict__ se2 = reinterpret_cast<float2*>(season + (size_t)blockIdx.x * ROW_N);
    const float2* __restrict__ xr2 = reinterpret_cast<const float2*>(xr);
    for (int q = tid; q <= O1 - 4; q += NTHREADS) {
        float e, o; wt_sfb_pair(P, q, e, o);
        const float2 xv = xr2[q];
        tr2[q] = make_float2(e, o);
        se2[q] = make_float2(xv.x - e, xv.y - o);
    }
}

extern "C" void kernel_launch(void* const* d_in, const int* in_sizes, int n_in,
                              void* d_out, int out_size) {
    const float* x = (const float*)d_in[0];
    float* out = (float*)d_out;
    const size_t half = (size_t)out_size / 2;     // 512*32768
    float* season = out;                           // tuple order: (season, trend)
    float* trend  = out + half;

    const int rows = in_sizes[0] / ROW_N;          // 512

    // >48KB dynamic smem opt-in (host-side attribute; not a stream op, capture-safe)
    cudaFuncSetAttribute(wt_series_decomp_kernel,
                         cudaFuncAttributeMaxDynamicSharedMemorySize, SMEM_BYTES);

    wt_series_decomp_kernel<<<rows, NTHREADS, SMEM_BYTES>>>(x, season, trend);
}

// round 3
// speedup vs baseline: 1.0907x; 1.0907x over previous
#include <cuda_runtime.h>

// ---------------------------------------------------------------------------
// 4-level db4 DWT low-pass analysis + synthesis, one CTA per row, all
// intermediates in SMEM. Register-blocked x4 with float4 LDS/STS/LDG.
//
// Analysis (stride 2, 8 taps, zero-pad 6):  out[o] = sum_j DEC_LO[7-j]*in[2o+j-6]
//   lengths 32768 -> 16387 -> 8197 -> 4102 -> 2054
// Synthesis (2x dilate, pad(1,1)), polyphase:
//   out[2q]   = D1*lo[q] + D3*lo[q+1] + D5*lo[q+2] + D7*lo[q+3]
//   out[2q+1] = D0*lo[q] + D2*lo[q+1] + D4*lo[q+2] + D6*lo[q+3]
//   q in [0, M-4];  2054 -> 4102 -> 8198(->8197) -> 16388(->16387) -> 32768
// Valid synthesis q reads lo[q..q+3] <= lo[M-1]: trim needs no re-zeroing.
// season = x - trend fused into last stage.
// ---------------------------------------------------------------------------

namespace {
constexpr int ROW_N = 32768;
constexpr int O1 = 16387, O2 = 8197, O3 = 4102, O4 = 2054;
constexpr int PCAP = 16388, QCAP = 8198;
constexpr int PRE = 8, MID = 24, POST = 24;          // zeroed halos
constexpr int P_OFF = PRE;
constexpr int Q_OFF = PRE + PCAP + MID;
constexpr int SMEM_FLOATS = PRE + PCAP + MID + QCAP + POST;   // 24642
constexpr int SMEM_BYTES = SMEM_FLOATS * 4;                   // 98568 -> 2 CTA/SM
constexpr int NT = 512;

// db4 DEC_LO taps
constexpr float D0 = -0.010597401784997278f;
constexpr float D1 =  0.032883011666982945f;
constexpr float D2 =  0.030841381835986965f;
constexpr float D3 = -0.18703481171888114f;
constexpr float D4 = -0.02798376941698385f;
constexpr float D5 =  0.6308807679295904f;
constexpr float D6 =  0.7148465705525415f;
constexpr float D7 =  0.23037781330885523f;
}

// Scalar analysis output with bounds checks (A1 edges only).
__device__ __forceinline__ float wt_afb8_edge(const float* __restrict__ in, int N, int o) {
    const int b = 2 * o - 6;
    float acc = 0.0f;
    const float h[8] = {D7, D6, D5, D4, D3, D2, D1, D0};
#pragma unroll
    for (int j = 0; j < 8; j++) {
        const int i = b + j;
        if ((unsigned)i < (unsigned)N) acc += h[j] * in[i];
    }
    return acc;
}

// Load 24-float window starting at in[w0] (w0 must be 16B aligned).
__device__ __forceinline__ void load24(const float* __restrict__ in, int w0, float* w) {
    const float4* p = reinterpret_cast<const float4*>(in + w0);
#pragma unroll
    for (int k = 0; k < 6; k++) {
        float4 v = p[k];
        w[4*k+0] = v.x; w[4*k+1] = v.y; w[4*k+2] = v.z; w[4*k+3] = v.w;
    }
}

// 4 analysis outputs o0..o0+3 from window w[] (w[k] = in[2*o0-8+k]).
__device__ __forceinline__ void afb4(const float* w, float* r) {
#pragma unroll
    for (int i = 0; i < 4; i++) {
        r[i] = D7 * w[2*i+2] + D6 * w[2*i+3] + D5 * w[2*i+4] + D4 * w[2*i+5]
             + D3 * w[2*i+6] + D2 * w[2*i+7] + D1 * w[2*i+8] + D0 * w[2*i+9];
    }
}

// SMEM analysis stage: in (halo-zeroed) -> out (len O), then zero out[O..O+8).
__device__ __forceinline__ void afb_stage_smem(const float* __restrict__ in,
                                               float* __restrict__ out,
                                               int O, int tid) {
    const int G = (O + 3) >> 2;
    for (int g = tid; g < G; g += NT) {
        const int o0 = 4 * g;
        float w[24]; load24(in, 2*o0 - 8, w);
        float r[4];  afb4(w, r);
        if (o0 + 4 <= O) {
            *reinterpret_cast<float4*>(out + o0) = make_float4(r[0], r[1], r[2], r[3]);
        } else {
#pragma unroll
            for (int i = 0; i < 4; i++) if (o0 + i < O) out[o0 + i] = r[i];
        }
    }
    if (tid < 8) out[O + tid] = 0.0f;   // zero taps beyond length for next stage
}

// SMEM synthesis stage: lo (effective len M) -> out (2M-6 valid; overshoot into halo ok).
__device__ __forceinline__ void sfb_stage_smem(const float* __restrict__ lo,
                                               float* __restrict__ out,
                                               int M, int tid) {
    const int G = M >> 2;                 // covers all valid q <= M-4
    for (int g = tid; g < G; g += NT) {
        const int q0 = 4 * g;
        const float4 u = *reinterpret_cast<const float4*>(lo + q0);
        const float4 v = *reinterpret_cast<const float4*>(lo + q0 + 4);
        const float l0=u.x, l1=u.y, l2=u.z, l3=u.w, l4=v.x, l5=v.y, l6=v.z;
        const float e0 = D1*l0 + D3*l1 + D5*l2 + D7*l3;
        const float o0_= D0*l0 + D2*l1 + D4*l2 + D6*l3;
        const float e1 = D1*l1 + D3*l2 + D5*l3 + D7*l4;
        const float o1_= D0*l1 + D2*l2 + D4*l3 + D6*l4;
        const float e2 = D1*l2 + D3*l3 + D5*l4 + D7*l5;
        const float o2_= D0*l2 + D2*l3 + D4*l4 + D6*l5;
        const float e3 = D1*l3 + D3*l4 + D5*l5 + D7*l6;
        const float o3_= D0*l3 + D2*l4 + D4*l5 + D6*l6;
        *reinterpret_cast<float4*>(out + 2*q0)     = make_float4(e0, o0_, e1, o1_);
        *reinterpret_cast<float4*>(out + 2*q0 + 4) = make_float4(e2, o2_, e3, o3_);
    }
}

__global__ void __launch_bounds__(NT, 2)
wt_series_decomp_kernel(const float* __restrict__ x,
                        float* __restrict__ season,
                        float* __restrict__ trend)
{
    extern __shared__ float sm[];
    float* P = sm + P_OFF;
    float* Q = sm + Q_OFF;
    const int tid = threadIdx.x;
    const float* __restrict__ xr = x + (size_t)blockIdx.x * ROW_N;

    // Zero halos (pre-P, mid, post-Q) before first SMEM read (covered by barrier after A1).
    if (tid < PRE)                          sm[tid] = 0.0f;
    if (tid >= 32 && tid < 32 + MID)        sm[PRE + PCAP + (tid - 32)] = 0.0f;
    if (tid >= 64 && tid < 64 + POST)       sm[Q_OFF + QCAP + (tid - 64)] = 0.0f;

    // ---- A1: global x (32768) -> P (16387) ----
    // Vector interior: o0 = 4..16376 (window [2o0-8, 2o0+15] fully in-bounds).
    for (int g = tid; g < 4094; g += NT) {
        const int o0 = 4 + 4 * g;
        float w[24]; load24(xr, 2*o0 - 8, w);
        float r[4];  afb4(w, r);
        *reinterpret_cast<float4*>(P + o0) = make_float4(r[0], r[1], r[2], r[3]);
    }
    if (tid < 11) {                 // edge outputs 0..3 and 16380..16386
        const int o = (tid < 4) ? tid : (16376 + tid);
        P[o] = wt_afb8_edge(xr, ROW_N, o);
    }
    if (tid >= 16 && tid < 24) P[O1 + (tid - 16)] = 0.0f;
    __syncthreads();

    afb_stage_smem(P, Q, O2, tid);  __syncthreads();   // A2
    afb_stage_smem(Q, P, O3, tid);  __syncthreads();   // A3
    afb_stage_smem(P, Q, O4, tid);  __syncthreads();   // A4

    sfb_stage_smem(Q, P, O4, tid);  __syncthreads();   // S1: 2054 -> 4102
    sfb_stage_smem(P, Q, O3, tid);  __syncthreads();   // S2: 4102 -> 8198
    sfb_stage_smem(Q, P, O2, tid);  __syncthreads();   // S3: 8197(eff) -> 16388

    // ---- S4 fused with season = x - trend, exact (16384 q's = 4096 groups) ----
    {
        float4* __restrict__ tr4 = reinterpret_cast<float4*>(trend + (size_t)blockIdx.x * ROW_N);
        float4* __restrict__ se4 = reinterpret_cast<float4*>(season + (size_t)blockIdx.x * ROW_N);
        const float4* __restrict__ xr4 = reinterpret_cast<const float4*>(xr);
        for (int g = tid; g < 4096; g += NT) {
            const int q0 = 4 * g;
            const float4 u = *reinterpret_cast<const float4*>(P + q0);
            const float4 v = *reinterpret_cast<const float4*>(P + q0 + 4);
            const float l0=u.x, l1=u.y, l2=u.z, l3=u.w, l4=v.x, l5=v.y, l6=v.z;
            const float e0 = D1*l0 + D3*l1 + D5*l2 + D7*l3;
            const float o0_= D0*l0 + D2*l1 + D4*l2 + D6*l3;
            const float e1 = D1*l1 + D3*l2 + D5*l3 + D7*l4;
            const float o1_= D0*l1 + D2*l2 + D4*l3 + D6*l4;
            const float e2 = D1*l2 + D3*l3 + D5*l4 + D7*l5;
            const float o2_= D0*l2 + D2*l3 + D4*l4 + D6*l5;
            const float e3 = D1*l3 + D3*l4 + D5*l5 + D7*l6;
            const float o3_= D0*l3 + D2*l4 + D4*l5 + D6*l6;
            const int i0 = q0 >> 1;                 // float4 index (2*q0 / 4)
            const float4 xa = xr4[i0];
            const float4 xb = xr4[i0 + 1];
            tr4[i0]     = make_float4(e0, o0_, e1, o1_);
            tr4[i0 + 1] = make_float4(e2, o2_, e3, o3_);
            se4[i0]     = make_float4(xa.x - e0, xa.y - o0_, xa.z - e1, xa.w - o1_);
            se4[i0 + 1] = make_float4(xb.x - e2, xb.y - o2_, xb.z - e3, xb.w - o3_);
        }
    }
}

extern "C" void kernel_launch(void* const* d_in, const int* in_sizes, int n_in,
                              void* d_out, int out_size) {
    const float* x = (const float*)d_in[0];
    float* out = (float*)d_out;
    const size_t half = (size_t)out_size / 2;     // 512*32768
    float* season = out;                           // tuple order: (season, trend)
    float* trend  = out + half;

    const int rows = in_sizes[0] / ROW_N;          // 512

    cudaFuncSetAttribute(wt_series_decomp_kernel,
                         cudaFuncAttributeMaxDynamicSharedMemorySize, SMEM_BYTES);

    wt_series_decomp_kernel<<<rows, NT, SMEM_BYTES>>>(x, season, trend);
}